// round 3
// baseline (speedup 1.0000x reference)
#include <cuda_runtime.h>
#include <cuda_bf16.h>

#define USER_NUM 200000
#define ITEM_NUM 100000
#define EMB 64
#define MAX_NE 3200000

// ---------------------------------------------------------------------------
// Scratch (__device__ globals; no allocation allowed)
// ---------------------------------------------------------------------------
__device__ float g_agg[(size_t)USER_NUM * EMB];     // 51.2 MB
__device__ float g_U[(size_t)USER_NUM * EMB];       // 51.2 MB
__device__ int2  g_csr_cv[MAX_NE];                  // 25.6 MB (col,val packed)
__device__ int   g_cnt[USER_NUM];
__device__ int   g_rs[USER_NUM];
__device__ int   g_cur[USER_NUM];
__device__ int   g_bsum[256];

// ---------------------------------------------------------------------------
// CSR build
// ---------------------------------------------------------------------------
__global__ void zero_int_kernel(int* __restrict__ p, int n) {
    int i = blockIdx.x * blockDim.x + threadIdx.x;
    if (i < n) p[i] = 0;
}

__global__ void hist_kernel(const int* __restrict__ rows, int* __restrict__ cnt, int ne) {
    int i = blockIdx.x * blockDim.x + threadIdx.x;
    if (i < ne) atomicAdd(&cnt[rows[i]], 1);
}

__device__ __forceinline__ int warp_excl_scan(int v, int lane, int* total) {
    int x = v;
    #pragma unroll
    for (int d = 1; d < 32; d <<= 1) {
        int y = __shfl_up_sync(0xffffffffu, x, d);
        if (lane >= d) x += y;
    }
    *total = __shfl_sync(0xffffffffu, x, 31);
    return x - v;
}

// per-block (1024 elems) sum
__global__ void block_sum_kernel(const int* __restrict__ cnt, int* __restrict__ bsum, int n) {
    __shared__ int wsum[8];
    int tid = threadIdx.x, lane = tid & 31, wid = tid >> 5;
    int base = blockIdx.x * 1024 + tid * 4;
    int s = 0;
    #pragma unroll
    for (int j = 0; j < 4; j++) { int idx = base + j; if (idx < n) s += cnt[idx]; }
    int tot; warp_excl_scan(s, lane, &tot);
    if (lane == 31) wsum[wid] = tot;
    __syncthreads();
    if (tid == 0) {
        int t = 0;
        #pragma unroll
        for (int w = 0; w < 8; w++) t += wsum[w];
        bsum[blockIdx.x] = t;
    }
}

// block-local exclusive scan; block offset derived inline from bsum[] (no
// separate scan_bsum kernel: each block sums bsum[0..bid)).
__global__ void scan_block_kernel(const int* __restrict__ cnt, const int* __restrict__ bsum,
                                  int* __restrict__ rs, int* __restrict__ cur,
                                  int n, int nb) {
    __shared__ int wsum[8];
    __shared__ int s_boff;
    int tid = threadIdx.x, lane = tid & 31, wid = tid >> 5;

    // ---- block offset = sum of bsum[t] for t < blockIdx.x ----
    int bv = (tid < nb && tid < blockIdx.x) ? bsum[tid] : 0;
    #pragma unroll
    for (int d = 16; d > 0; d >>= 1) bv += __shfl_down_sync(0xffffffffu, bv, d);
    if (lane == 0) wsum[wid] = bv;
    __syncthreads();
    if (tid == 0) {
        int t = 0;
        #pragma unroll
        for (int w = 0; w < 8; w++) t += wsum[w];
        s_boff = t;
    }
    __syncthreads();
    int boff = s_boff;
    __syncthreads();   // wsum reused below

    // ---- local exclusive scan of 1024 counts ----
    int base = blockIdx.x * 1024 + tid * 4;
    int v[4]; int s = 0;
    #pragma unroll
    for (int j = 0; j < 4; j++) { int idx = base + j; v[j] = (idx < n) ? cnt[idx] : 0; s += v[j]; }
    int wtot; int ex = warp_excl_scan(s, lane, &wtot);
    if (lane == 31) wsum[wid] = wtot;
    __syncthreads();
    if (wid == 0) {
        int t = (lane < 8) ? wsum[lane] : 0;
        int tt; int e = warp_excl_scan(t, lane, &tt);
        if (lane < 8) wsum[lane] = e;
    }
    __syncthreads();
    int off = boff + wsum[wid] + ex;
    #pragma unroll
    for (int j = 0; j < 4; j++) {
        int idx = base + j;
        if (idx < n) { rs[idx] = off; cur[idx] = off; off += v[j]; }
    }
}

__global__ void scatter_kernel(const int* __restrict__ rows, const int* __restrict__ cols,
                               const float* __restrict__ vals, int* __restrict__ cur,
                               int2* __restrict__ cv, int ne) {
    int i = blockIdx.x * blockDim.x + threadIdx.x;
    if (i >= ne) return;
    int r = rows[i];
    int p = atomicAdd(&cur[r], 1);
    cv[p] = make_int2(cols[i], __float_as_int(vals[i]));
}

// ---------------------------------------------------------------------------
// CSR SpMM: 16 threads per output row, register accumulation, no atomics.
// ---------------------------------------------------------------------------
__global__ void __launch_bounds__(256)
spmm_csr_kernel(const int* __restrict__ rs, const int* __restrict__ cnt,
                const int2* __restrict__ cv,
                const float4* __restrict__ X4, float4* __restrict__ out4,
                int accumulate) {
    long long t = (long long)blockIdx.x * blockDim.x + threadIdx.x;
    int row = (int)(t >> 4);
    int g   = (int)(t & 15);
    if (row >= USER_NUM) return;
    int s = rs[row];
    int e = s + cnt[row];
    float4 acc;
    if (accumulate) acc = out4[(long long)row * 16 + g];
    else            acc = make_float4(0.f, 0.f, 0.f, 0.f);
    for (int i = s; i < e; i++) {
        int2  p = __ldg(&cv[i]);
        float v = __int_as_float(p.y);
        float4 x = X4[(long long)p.x * 16 + g];
        acc.x += v * x.x; acc.y += v * x.y; acc.z += v * x.z; acc.w += v * x.w;
    }
    out4[(long long)row * 16 + g] = acc;
}

// ---------------------------------------------------------------------------
// Fused GEMM + bias + ReLU with packed f32x2 FMA.
//   out[r,o] = relu( sum_k h[r,k]*W[o,k] + b[o] ),  h = concat(agg, U)
// Shared:
//   hstd[k][2r]   : h duplicated -> (h,h) register pairs for free (broadcast LDS)
//   ws[k][o]      : o-contiguous -> (W[o0],W[o1]) pairs for free
// Inner loop per k: 3x LDS.128 + 8x fma.rn.f32x2 (no packing movs).
// ---------------------------------------------------------------------------
#define HSTD_STRIDE 128                         // floats per k-row (64 rows dup)
#define WS_STRIDE   68
#define GEMM_SMEM   ((128 * HSTD_STRIDE + 128 * WS_STRIDE) * 4)   // 100,352 B

__device__ __forceinline__ void fma2(unsigned long long& d,
                                     unsigned long long a,
                                     unsigned long long b) {
    asm("fma.rn.f32x2 %0, %1, %2, %0;" : "+l"(d) : "l"(a), "l"(b));
}
__device__ __forceinline__ unsigned long long dup32(float x) {
    unsigned int u = __float_as_uint(x);
    return ((unsigned long long)u << 32) | u;
}

__global__ void __launch_bounds__(256, 2)
gemm_relu_kernel(const float4* __restrict__ agg4,
                 const float4* __restrict__ u4,
                 const float4* __restrict__ W4,   // [64][32] float4 of [64][128]
                 const float*  __restrict__ bias,
                 float4* __restrict__ out4) {
    extern __shared__ float smem[];
    float* hstd = smem;                        // 128 k x 128 (64 rows dup)
    float* ws   = smem + 128 * HSTD_STRIDE;    // 128 k x 68

    int tid = threadIdx.x;
    long long block_row = (long long)blockIdx.x * 64;

    // h tile, duplicated per element: hstd[k][2r]=hstd[k][2r+1]=h[r][k]
    #pragma unroll
    for (int i = tid; i < 64 * 32; i += 256) {
        int r = i & 63, c = i >> 6;            // warp: fixed c, r consecutive
        long long grow = block_row + r;
        float4 v = (c < 16) ? agg4[grow * 16 + c] : u4[grow * 16 + (c - 16)];
        int k0 = 4 * c;
        float vv[4] = {v.x, v.y, v.z, v.w};
        #pragma unroll
        for (int j = 0; j < 4; j++)
            *(unsigned long long*)&hstd[(k0 + j) * HSTD_STRIDE + 2 * r] = dup32(vv[j]);
    }
    // W transposed: ws[k][o] = W[o][k]
    #pragma unroll
    for (int i = tid; i < 64 * 32; i += 256) {
        int o = i & 63, c = i >> 6;
        float4 w = W4[o * 32 + c];
        ws[(4 * c + 0) * WS_STRIDE + o] = w.x;
        ws[(4 * c + 1) * WS_STRIDE + o] = w.y;
        ws[(4 * c + 2) * WS_STRIDE + o] = w.z;
        ws[(4 * c + 3) * WS_STRIDE + o] = w.w;
    }
    __syncthreads();

    int tx = tid & 15, ty = tid >> 4;
    int o0 = tx * 4;
    unsigned long long acc[4][2] = {};         // [row][o-pair]: (o0,o1),(o2,o3)

    #pragma unroll 8
    for (int k = 0; k < 128; k++) {
        // (W[o0,k],W[o1,k]) and (W[o2,k],W[o3,k]) — contiguous, one LDS.128
        ulonglong2 wp = *(const ulonglong2*)&ws[k * WS_STRIDE + o0];
        // (h,h) pairs for rows 4ty..4ty+3 — duplicated in shared, two LDS.128
        ulonglong2 h01 = *(const ulonglong2*)&hstd[k * HSTD_STRIDE + 8 * ty];
        ulonglong2 h23 = *(const ulonglong2*)&hstd[k * HSTD_STRIDE + 8 * ty + 4];
        fma2(acc[0][0], wp.x, h01.x);  fma2(acc[0][1], wp.y, h01.x);
        fma2(acc[1][0], wp.x, h01.y);  fma2(acc[1][1], wp.y, h01.y);
        fma2(acc[2][0], wp.x, h23.x);  fma2(acc[2][1], wp.y, h23.x);
        fma2(acc[3][0], wp.x, h23.y);  fma2(acc[3][1], wp.y, h23.y);
    }

    float b0 = bias[o0 + 0], b1 = bias[o0 + 1], b2 = bias[o0 + 2], b3 = bias[o0 + 3];
    #pragma unroll
    for (int ri = 0; ri < 4; ri++) {
        long long r = block_row + ty * 4 + ri;
        float4 v;
        v.x = fmaxf(__uint_as_float((unsigned int)(acc[ri][0]))       + b0, 0.f);
        v.y = fmaxf(__uint_as_float((unsigned int)(acc[ri][0] >> 32)) + b1, 0.f);
        v.z = fmaxf(__uint_as_float((unsigned int)(acc[ri][1]))       + b2, 0.f);
        v.w = fmaxf(__uint_as_float((unsigned int)(acc[ri][1] >> 32)) + b3, 0.f);
        out4[r * 16 + tx] = v;
    }
}

// ---------------------------------------------------------------------------
// Launch
// ---------------------------------------------------------------------------
static void build_csr(const int* rows, const int* cols, const float* vals, int ne,
                      int* cnt, int* rs, int* cur, int* bsum, int2* cv) {
    const int nb_scan = (USER_NUM + 1023) / 1024;          // 196
    const int eb = (ne + 255) / 256;
    zero_int_kernel<<<(USER_NUM + 255) / 256, 256>>>(cnt, USER_NUM);
    hist_kernel<<<eb, 256>>>(rows, cnt, ne);
    block_sum_kernel<<<nb_scan, 256>>>(cnt, bsum, USER_NUM);
    scan_block_kernel<<<nb_scan, 256>>>(cnt, bsum, rs, cur, USER_NUM, nb_scan);
    scatter_kernel<<<eb, 256>>>(rows, cols, vals, cur, cv, ne);
}

extern "C" void kernel_launch(void* const* d_in, const int* in_sizes, int n_in,
                              void* d_out, int out_size) {
    const float* user_emb = (const float*)d_in[0];
    const float* item_emb = (const float*)d_in[1];
    const float* W        = (const float*)d_in[2];
    const float* b        = (const float*)d_in[3];
    const int*   s_rows   = (const int*)  d_in[4];
    const int*   s_cols   = (const int*)  d_in[5];
    const float* s_vals   = (const float*)d_in[6];
    const int*   r_rows   = (const int*)  d_in[7];
    const int*   r_cols   = (const int*)  d_in[8];
    const float* r_vals   = (const float*)d_in[9];
    int ne_s = in_sizes[4];
    int ne_r = in_sizes[7];

    float* out_user = (float*)d_out;
    float* out_item = out_user + (size_t)USER_NUM * EMB;

    float *agg, *U1;
    int *cnt, *rs, *cur, *bsum;
    int2 *cv;
    cudaGetSymbolAddress((void**)&agg,  g_agg);
    cudaGetSymbolAddress((void**)&U1,   g_U);
    cudaGetSymbolAddress((void**)&cnt,  g_cnt);
    cudaGetSymbolAddress((void**)&rs,   g_rs);
    cudaGetSymbolAddress((void**)&cur,  g_cur);
    cudaGetSymbolAddress((void**)&bsum, g_bsum);
    cudaGetSymbolAddress((void**)&cv,   g_csr_cv);

    cudaFuncSetAttribute(gemm_relu_kernel,
                         cudaFuncAttributeMaxDynamicSharedMemorySize, GEMM_SMEM);

    const int spmm_gb = (USER_NUM * 16 + 255) / 256;   // 12500
    const int gemm_gb = USER_NUM / 64;                 // 3125

    // ---- CSR(S) build (reused by both layers) ----
    build_csr(s_rows, s_cols, s_vals, ne_s, cnt, rs, cur, bsum, cv);

    // Layer 0
    spmm_csr_kernel<<<spmm_gb, 256>>>(rs, cnt, cv, (const float4*)user_emb,
                                      (float4*)agg, 0);
    gemm_relu_kernel<<<gemm_gb, 256, GEMM_SMEM>>>((const float4*)agg, (const float4*)user_emb,
                                                  (const float4*)W, b, (float4*)U1);
    // Layer 1
    spmm_csr_kernel<<<spmm_gb, 256>>>(rs, cnt, cv, (const float4*)U1,
                                      (float4*)agg, 0);
    gemm_relu_kernel<<<gemm_gb, 256, GEMM_SMEM>>>((const float4*)agg, (const float4*)U1,
                                                  (const float4*)(W + 64 * 128), b + 64,
                                                  (float4*)out_user);

    // ---- CSR(R) build + final accumulate SpMM ----
    build_csr(r_rows, r_cols, r_vals, ne_r, cnt, rs, cur, bsum, cv);
    spmm_csr_kernel<<<spmm_gb, 256>>>(rs, cnt, cv, (const float4*)item_emb,
                                      (float4*)out_user, 1);

    // item_all = V
    cudaMemcpyAsync(out_item, item_emb, (size_t)ITEM_NUM * EMB * sizeof(float),
                    cudaMemcpyDeviceToDevice, 0);
}

// round 4
// speedup vs baseline: 1.1346x; 1.1346x over previous
#include <cuda_runtime.h>
#include <cuda_bf16.h>

#define USER_NUM 200000
#define ITEM_NUM 100000
#define EMB 64
#define MAX_NE 3200000

// ---------------------------------------------------------------------------
// Scratch (__device__ globals; no allocation allowed)
// ---------------------------------------------------------------------------
__device__ float g_agg[(size_t)USER_NUM * EMB];     // 51.2 MB
__device__ float g_U[(size_t)USER_NUM * EMB];       // 51.2 MB
// CSR(S)
__device__ int2  g_cvS[MAX_NE];
__device__ int   g_cntS[USER_NUM];
__device__ int   g_rsS[USER_NUM];
__device__ int   g_curS[USER_NUM];
__device__ int   g_bsumS[256];
// CSR(R) — separate buffers so the build can run on a side stream
__device__ int2  g_cvR[MAX_NE];
__device__ int   g_cntR[USER_NUM];
__device__ int   g_rsR[USER_NUM];
__device__ int   g_curR[USER_NUM];
__device__ int   g_bsumR[256];

// ---------------------------------------------------------------------------
// Streams/events for in-graph fork-join (created once at load; kernel_launch
// itself performs the same deterministic work every call).
// ---------------------------------------------------------------------------
static cudaStream_t s_side = nullptr;
static cudaEvent_t  s_ev_fork = nullptr, s_ev_join = nullptr;
namespace {
struct SideInit {
    SideInit() {
        cudaStreamCreateWithFlags(&s_side, cudaStreamNonBlocking);
        cudaEventCreateWithFlags(&s_ev_fork, cudaEventDisableTiming);
        cudaEventCreateWithFlags(&s_ev_join, cudaEventDisableTiming);
    }
} s_side_init;
}

// ---------------------------------------------------------------------------
// CSR build kernels
// ---------------------------------------------------------------------------
__global__ void zero_int_kernel(int* __restrict__ p, int n) {
    int i = blockIdx.x * blockDim.x + threadIdx.x;
    if (i < n) p[i] = 0;
}

__global__ void hist_kernel(const int* __restrict__ rows, int* __restrict__ cnt, int ne) {
    int i = blockIdx.x * blockDim.x + threadIdx.x;
    if (i < ne) atomicAdd(&cnt[rows[i]], 1);
}

__device__ __forceinline__ int warp_excl_scan(int v, int lane, int* total) {
    int x = v;
    #pragma unroll
    for (int d = 1; d < 32; d <<= 1) {
        int y = __shfl_up_sync(0xffffffffu, x, d);
        if (lane >= d) x += y;
    }
    *total = __shfl_sync(0xffffffffu, x, 31);
    return x - v;
}

__global__ void block_sum_kernel(const int* __restrict__ cnt, int* __restrict__ bsum, int n) {
    __shared__ int wsum[8];
    int tid = threadIdx.x, lane = tid & 31, wid = tid >> 5;
    int base = blockIdx.x * 1024 + tid * 4;
    int s = 0;
    #pragma unroll
    for (int j = 0; j < 4; j++) { int idx = base + j; if (idx < n) s += cnt[idx]; }
    int tot; warp_excl_scan(s, lane, &tot);
    if (lane == 31) wsum[wid] = tot;
    __syncthreads();
    if (tid == 0) {
        int t = 0;
        #pragma unroll
        for (int w = 0; w < 8; w++) t += wsum[w];
        bsum[blockIdx.x] = t;
    }
}

// block-local exclusive scan; block offset derived inline from bsum[]
__global__ void scan_block_kernel(const int* __restrict__ cnt, const int* __restrict__ bsum,
                                  int* __restrict__ rs, int* __restrict__ cur,
                                  int n, int nb) {
    __shared__ int wsum[8];
    __shared__ int s_boff;
    int tid = threadIdx.x, lane = tid & 31, wid = tid >> 5;

    int bv = (tid < nb && tid < blockIdx.x) ? bsum[tid] : 0;
    #pragma unroll
    for (int d = 16; d > 0; d >>= 1) bv += __shfl_down_sync(0xffffffffu, bv, d);
    if (lane == 0) wsum[wid] = bv;
    __syncthreads();
    if (tid == 0) {
        int t = 0;
        #pragma unroll
        for (int w = 0; w < 8; w++) t += wsum[w];
        s_boff = t;
    }
    __syncthreads();
    int boff = s_boff;
    __syncthreads();

    int base = blockIdx.x * 1024 + tid * 4;
    int v[4]; int s = 0;
    #pragma unroll
    for (int j = 0; j < 4; j++) { int idx = base + j; v[j] = (idx < n) ? cnt[idx] : 0; s += v[j]; }
    int wtot; int ex = warp_excl_scan(s, lane, &wtot);
    if (lane == 31) wsum[wid] = wtot;
    __syncthreads();
    if (wid == 0) {
        int t = (lane < 8) ? wsum[lane] : 0;
        int tt; int e = warp_excl_scan(t, lane, &tt);
        if (lane < 8) wsum[lane] = e;
    }
    __syncthreads();
    int off = boff + wsum[wid] + ex;
    #pragma unroll
    for (int j = 0; j < 4; j++) {
        int idx = base + j;
        if (idx < n) { rs[idx] = off; cur[idx] = off; off += v[j]; }
    }
}

__global__ void scatter_kernel(const int* __restrict__ rows, const int* __restrict__ cols,
                               const float* __restrict__ vals, int* __restrict__ cur,
                               int2* __restrict__ cv, int ne) {
    int i = blockIdx.x * blockDim.x + threadIdx.x;
    if (i >= ne) return;
    int r = rows[i];
    int p = atomicAdd(&cur[r], 1);
    cv[p] = make_int2(cols[i], __float_as_int(vals[i]));
}

// ---------------------------------------------------------------------------
// CSR SpMM: 16 threads per output row, register accumulation, no atomics.
// ---------------------------------------------------------------------------
__global__ void __launch_bounds__(256)
spmm_csr_kernel(const int* __restrict__ rs, const int* __restrict__ cnt,
                const int2* __restrict__ cv,
                const float4* __restrict__ X4, float4* __restrict__ out4,
                int accumulate) {
    long long t = (long long)blockIdx.x * blockDim.x + threadIdx.x;
    int row = (int)(t >> 4);
    int g   = (int)(t & 15);
    if (row >= USER_NUM) return;
    int s = rs[row];
    int e = s + cnt[row];
    float4 acc;
    if (accumulate) acc = out4[(long long)row * 16 + g];
    else            acc = make_float4(0.f, 0.f, 0.f, 0.f);
    for (int i = s; i < e; i++) {
        int2  p = __ldg(&cv[i]);
        float v = __int_as_float(p.y);
        float4 x = X4[(long long)p.x * 16 + g];
        acc.x += v * x.x; acc.y += v * x.y; acc.z += v * x.z; acc.w += v * x.w;
    }
    out4[(long long)row * 16 + g] = acc;
}

// ---------------------------------------------------------------------------
// Fused GEMM + bias + ReLU (R2 scalar-FFMA version — known good)
// ---------------------------------------------------------------------------
#define HS_STRIDE 132
#define WS_STRIDE 68
#define GEMM_SMEM ((64 * HS_STRIDE + 128 * WS_STRIDE) * 4)   // 68,608 B

__global__ void __launch_bounds__(256, 3)
gemm_relu_kernel(const float4* __restrict__ agg4,
                 const float4* __restrict__ u4,
                 const float4* __restrict__ W4,
                 const float*  __restrict__ bias,
                 float4* __restrict__ out4) {
    extern __shared__ float smem[];
    float* hs = smem;
    float* ws = smem + 64 * HS_STRIDE;

    int tid = threadIdx.x;
    long long block_row = (long long)blockIdx.x * 64;

    #pragma unroll
    for (int i = tid; i < 64 * 32; i += 256) {
        int r = i >> 5, c = i & 31;
        long long grow = block_row + r;
        float4 v = (c < 16) ? agg4[grow * 16 + c] : u4[grow * 16 + (c - 16)];
        *(float4*)&hs[r * HS_STRIDE + c * 4] = v;
    }
    #pragma unroll
    for (int i = tid; i < 64 * 32; i += 256) {
        int o = i & 63, c = i >> 6;
        float4 w = W4[o * 32 + c];
        ws[(4 * c + 0) * WS_STRIDE + o] = w.x;
        ws[(4 * c + 1) * WS_STRIDE + o] = w.y;
        ws[(4 * c + 2) * WS_STRIDE + o] = w.z;
        ws[(4 * c + 3) * WS_STRIDE + o] = w.w;
    }
    __syncthreads();

    int tx = tid & 15, ty = tid >> 4;
    int o0 = tx * 4;
    float acc[4][4] = {};

    #pragma unroll 4
    for (int k4 = 0; k4 < 32; k4++) {
        float4 wv[4];
        #pragma unroll
        for (int j = 0; j < 4; j++)
            wv[j] = *(const float4*)&ws[(4 * k4 + j) * WS_STRIDE + o0];
        #pragma unroll
        for (int ri = 0; ri < 4; ri++) {
            int r = ty * 4 + ri;
            float4 hv = *(const float4*)&hs[r * HS_STRIDE + k4 * 4];
            acc[ri][0] += hv.x * wv[0].x + hv.y * wv[1].x + hv.z * wv[2].x + hv.w * wv[3].x;
            acc[ri][1] += hv.x * wv[0].y + hv.y * wv[1].y + hv.z * wv[2].y + hv.w * wv[3].y;
            acc[ri][2] += hv.x * wv[0].z + hv.y * wv[1].z + hv.z * wv[2].z + hv.w * wv[3].z;
            acc[ri][3] += hv.x * wv[0].w + hv.y * wv[1].w + hv.z * wv[2].w + hv.w * wv[3].w;
        }
    }

    float b0 = bias[o0 + 0], b1 = bias[o0 + 1], b2 = bias[o0 + 2], b3 = bias[o0 + 3];
    #pragma unroll
    for (int ri = 0; ri < 4; ri++) {
        long long r = block_row + ty * 4 + ri;
        float4 v;
        v.x = fmaxf(acc[ri][0] + b0, 0.f);
        v.y = fmaxf(acc[ri][1] + b1, 0.f);
        v.z = fmaxf(acc[ri][2] + b2, 0.f);
        v.w = fmaxf(acc[ri][3] + b3, 0.f);
        out4[r * 16 + tx] = v;
    }
}

// ---------------------------------------------------------------------------
// Launch
// ---------------------------------------------------------------------------
static void build_csr(cudaStream_t st,
                      const int* rows, const int* cols, const float* vals, int ne,
                      int* cnt, int* rs, int* cur, int* bsum, int2* cv) {
    const int nb_scan = (USER_NUM + 1023) / 1024;          // 196
    const int eb = (ne + 255) / 256;
    zero_int_kernel<<<(USER_NUM + 255) / 256, 256, 0, st>>>(cnt, USER_NUM);
    hist_kernel<<<eb, 256, 0, st>>>(rows, cnt, ne);
    block_sum_kernel<<<nb_scan, 256, 0, st>>>(cnt, bsum, USER_NUM);
    scan_block_kernel<<<nb_scan, 256, 0, st>>>(cnt, bsum, rs, cur, USER_NUM, nb_scan);
    scatter_kernel<<<eb, 256, 0, st>>>(rows, cols, vals, cur, cv, ne);
}

extern "C" void kernel_launch(void* const* d_in, const int* in_sizes, int n_in,
                              void* d_out, int out_size) {
    const float* user_emb = (const float*)d_in[0];
    const float* item_emb = (const float*)d_in[1];
    const float* W        = (const float*)d_in[2];
    const float* b        = (const float*)d_in[3];
    const int*   s_rows   = (const int*)  d_in[4];
    const int*   s_cols   = (const int*)  d_in[5];
    const float* s_vals   = (const float*)d_in[6];
    const int*   r_rows   = (const int*)  d_in[7];
    const int*   r_cols   = (const int*)  d_in[8];
    const float* r_vals   = (const float*)d_in[9];
    int ne_s = in_sizes[4];
    int ne_r = in_sizes[7];

    float* out_user = (float*)d_out;
    float* out_item = out_user + (size_t)USER_NUM * EMB;

    float *agg, *U1;
    int *cntS, *rsS, *curS, *bsumS, *cntR, *rsR, *curR, *bsumR;
    int2 *cvS, *cvR;
    cudaGetSymbolAddress((void**)&agg,   g_agg);
    cudaGetSymbolAddress((void**)&U1,    g_U);
    cudaGetSymbolAddress((void**)&cntS,  g_cntS);
    cudaGetSymbolAddress((void**)&rsS,   g_rsS);
    cudaGetSymbolAddress((void**)&curS,  g_curS);
    cudaGetSymbolAddress((void**)&bsumS, g_bsumS);
    cudaGetSymbolAddress((void**)&cvS,   g_cvS);
    cudaGetSymbolAddress((void**)&cntR,  g_cntR);
    cudaGetSymbolAddress((void**)&rsR,   g_rsR);
    cudaGetSymbolAddress((void**)&curR,  g_curR);
    cudaGetSymbolAddress((void**)&bsumR, g_bsumR);
    cudaGetSymbolAddress((void**)&cvR,   g_cvR);

    cudaFuncSetAttribute(gemm_relu_kernel,
                         cudaFuncAttributeMaxDynamicSharedMemorySize, GEMM_SMEM);

    const int spmm_gb = (USER_NUM * 16 + 255) / 256;   // 12500
    const int gemm_gb = USER_NUM / 64;                 // 3125
    cudaStream_t s0 = 0;

    // ---- Fork side stream: CSR(R) build + item copy (independent of layers) ----
    cudaEventRecord(s_ev_fork, s0);
    cudaStreamWaitEvent(s_side, s_ev_fork, 0);
    build_csr(s_side, r_rows, r_cols, r_vals, ne_r, cntR, rsR, curR, bsumR, cvR);
    cudaMemcpyAsync(out_item, item_emb, (size_t)ITEM_NUM * EMB * sizeof(float),
                    cudaMemcpyDeviceToDevice, s_side);
    cudaEventRecord(s_ev_join, s_side);

    // ---- Main path: CSR(S) build + 2 layers ----
    build_csr(s0, s_rows, s_cols, s_vals, ne_s, cntS, rsS, curS, bsumS, cvS);

    spmm_csr_kernel<<<spmm_gb, 256, 0, s0>>>(rsS, cntS, cvS, (const float4*)user_emb,
                                             (float4*)agg, 0);
    gemm_relu_kernel<<<gemm_gb, 256, GEMM_SMEM, s0>>>((const float4*)agg, (const float4*)user_emb,
                                                      (const float4*)W, b, (float4*)U1);
    spmm_csr_kernel<<<spmm_gb, 256, 0, s0>>>(rsS, cntS, cvS, (const float4*)U1,
                                             (float4*)agg, 0);
    gemm_relu_kernel<<<gemm_gb, 256, GEMM_SMEM, s0>>>((const float4*)agg, (const float4*)U1,
                                                      (const float4*)(W + 64 * 128), b + 64,
                                                      (float4*)out_user);

    // ---- Join + final accumulate SpMM (needs CSR(R) and layer-1 output) ----
    cudaStreamWaitEvent(s0, s_ev_join, 0);
    spmm_csr_kernel<<<spmm_gb, 256, 0, s0>>>(rsR, cntR, cvR, (const float4*)item_emb,
                                             (float4*)out_user, 1);
}

// round 6
// speedup vs baseline: 1.1558x; 1.0186x over previous
#include <cuda_runtime.h>
#include <cuda_bf16.h>

#define USER_NUM 200000
#define ITEM_NUM 100000
#define EMB 64
#define MAX_NE 3200000

// ---------------------------------------------------------------------------
// Scratch (__device__ globals; no allocation allowed)
// ---------------------------------------------------------------------------
__device__ float g_U[(size_t)USER_NUM * EMB];       // 51.2 MB (layer-1 input)
__device__ int2  g_cv[MAX_NE];                      // CSR (col,val), reused S then R
__device__ int   g_cnt[USER_NUM];
__device__ int   g_rs[USER_NUM];
__device__ int   g_cur[USER_NUM];
__device__ int   g_bsum[256];
// second CSR set so S build survives for layer 1 while R builds
__device__ int2  g_cvR[MAX_NE];
__device__ int   g_cntR[USER_NUM];
__device__ int   g_rsR[USER_NUM];
__device__ int   g_curR[USER_NUM];
__device__ int   g_bsumR[256];

// ---------------------------------------------------------------------------
// CSR build kernels
// ---------------------------------------------------------------------------
__global__ void zero_int_kernel(int* __restrict__ p, int n) {
    int i = blockIdx.x * blockDim.x + threadIdx.x;
    if (i < n) p[i] = 0;
}

__global__ void hist_kernel(const int* __restrict__ rows, int* __restrict__ cnt, int ne) {
    int i = blockIdx.x * blockDim.x + threadIdx.x;
    if (i < ne) atomicAdd(&cnt[rows[i]], 1);
}

__device__ __forceinline__ int warp_excl_scan(int v, int lane, int* total) {
    int x = v;
    #pragma unroll
    for (int d = 1; d < 32; d <<= 1) {
        int y = __shfl_up_sync(0xffffffffu, x, d);
        if (lane >= d) x += y;
    }
    *total = __shfl_sync(0xffffffffu, x, 31);
    return x - v;
}

__global__ void block_sum_kernel(const int* __restrict__ cnt, int* __restrict__ bsum, int n) {
    __shared__ int wsum[8];
    int tid = threadIdx.x, lane = tid & 31, wid = tid >> 5;
    int base = blockIdx.x * 1024 + tid * 4;
    int s = 0;
    #pragma unroll
    for (int j = 0; j < 4; j++) { int idx = base + j; if (idx < n) s += cnt[idx]; }
    int tot; warp_excl_scan(s, lane, &tot);
    if (lane == 31) wsum[wid] = tot;
    __syncthreads();
    if (tid == 0) {
        int t = 0;
        #pragma unroll
        for (int w = 0; w < 8; w++) t += wsum[w];
        bsum[blockIdx.x] = t;
    }
}

__global__ void scan_block_kernel(const int* __restrict__ cnt, const int* __restrict__ bsum,
                                  int* __restrict__ rs, int* __restrict__ cur,
                                  int n, int nb) {
    __shared__ int wsum[8];
    __shared__ int s_boff;
    int tid = threadIdx.x, lane = tid & 31, wid = tid >> 5;

    int bv = (tid < nb && tid < blockIdx.x) ? bsum[tid] : 0;
    #pragma unroll
    for (int d = 16; d > 0; d >>= 1) bv += __shfl_down_sync(0xffffffffu, bv, d);
    if (lane == 0) wsum[wid] = bv;
    __syncthreads();
    if (tid == 0) {
        int t = 0;
        #pragma unroll
        for (int w = 0; w < 8; w++) t += wsum[w];
        s_boff = t;
    }
    __syncthreads();
    int boff = s_boff;
    __syncthreads();

    int base = blockIdx.x * 1024 + tid * 4;
    int v[4]; int s = 0;
    #pragma unroll
    for (int j = 0; j < 4; j++) { int idx = base + j; v[j] = (idx < n) ? cnt[idx] : 0; s += v[j]; }
    int wtot; int ex = warp_excl_scan(s, lane, &wtot);
    if (lane == 31) wsum[wid] = wtot;
    __syncthreads();
    if (wid == 0) {
        int t = (lane < 8) ? wsum[lane] : 0;
        int tt; int e = warp_excl_scan(t, lane, &tt);
        if (lane < 8) wsum[lane] = e;
    }
    __syncthreads();
    int off = boff + wsum[wid] + ex;
    #pragma unroll
    for (int j = 0; j < 4; j++) {
        int idx = base + j;
        if (idx < n) { rs[idx] = off; cur[idx] = off; off += v[j]; }
    }
}

__global__ void scatter_kernel(const int* __restrict__ rows, const int* __restrict__ cols,
                               const float* __restrict__ vals, int* __restrict__ cur,
                               int2* __restrict__ cv, int ne) {
    int i = blockIdx.x * blockDim.x + threadIdx.x;
    if (i >= ne) return;
    int r = rows[i];
    int p = atomicAdd(&cur[r], 1);
    cv[p] = make_int2(cols[i], __float_as_int(vals[i]));
}

// ---------------------------------------------------------------------------
// Standalone CSR SpMM (final R @ V accumulate)
// ---------------------------------------------------------------------------
__global__ void __launch_bounds__(256)
spmm_csr_kernel(const int* __restrict__ rs, const int* __restrict__ cnt,
                const int2* __restrict__ cv,
                const float4* __restrict__ X4, float4* __restrict__ out4) {
    long long t = (long long)blockIdx.x * blockDim.x + threadIdx.x;
    int row = (int)(t >> 4);
    int g   = (int)(t & 15);
    if (row >= USER_NUM) return;
    int s = rs[row];
    int e = s + cnt[row];
    float4 acc = out4[(long long)row * 16 + g];
    for (int i = s; i < e; i++) {
        int2  p = __ldg(&cv[i]);
        float v = __int_as_float(p.y);
        float4 x = X4[(long long)p.x * 16 + g];
        acc.x += v * x.x; acc.y += v * x.y; acc.z += v * x.z; acc.w += v * x.w;
    }
    out4[(long long)row * 16 + g] = acc;
}

// ---------------------------------------------------------------------------
// FUSED layer kernel: per 64-row block,
//   phase 1: CSR gather (agg) straight into shared h-tile cols [0,64)
//            + U tile load into h-tile cols [64,128) + W load/transpose
//   phase 2: the proven R2 GEMM (bias + ReLU) from shared
// No agg gmem round-trip; gather (LTS) and FMA phases overlap across blocks.
// ---------------------------------------------------------------------------
#define HS_STRIDE 132
#define WS_STRIDE 68
#define GEMM_SMEM ((64 * HS_STRIDE + 128 * WS_STRIDE) * 4)   // 68,608 B

__global__ void __launch_bounds__(256, 3)
fused_layer_kernel(const int* __restrict__ rs, const int* __restrict__ cnt,
                   const int2* __restrict__ cv,
                   const float4* __restrict__ X4,   // prev layer U [USER_NUM][16]
                   const float4* __restrict__ W4,   // [64][32] float4 of [64][128]
                   const float*  __restrict__ bias,
                   float4* __restrict__ out4) {
    extern __shared__ float smem[];
    float* hs = smem;                       // 64 x 132
    float* ws = smem + 64 * HS_STRIDE;      // 128 x 68

    int tid = threadIdx.x;
    long long block_row = (long long)blockIdx.x * 64;

    // ---- W load + transpose (independent of gather) ----
    #pragma unroll
    for (int i = tid; i < 64 * 32; i += 256) {
        int o = i & 63, c = i >> 6;
        float4 w = W4[o * 32 + c];
        ws[(4 * c + 0) * WS_STRIDE + o] = w.x;
        ws[(4 * c + 1) * WS_STRIDE + o] = w.y;
        ws[(4 * c + 2) * WS_STRIDE + o] = w.z;
        ws[(4 * c + 3) * WS_STRIDE + o] = w.w;
    }
    // ---- U half of h-tile: hs[r][64 + 4c .. 64+4c+3] = U[row][4c..] ----
    #pragma unroll
    for (int i = tid; i < 64 * 16; i += 256) {
        int r = i >> 4, c = i & 15;
        *(float4*)&hs[r * HS_STRIDE + 64 + c * 4] = X4[(block_row + r) * 16 + c];
    }

    // ---- SpMM phase: agg for this block's 64 rows -> hs cols [0,64) ----
    {
        int sub = tid >> 4;       // 0..15 (row slot)
        int g   = tid & 15;       // col group: floats 4g..4g+3
        #pragma unroll
        for (int j = 0; j < 4; j++) {
            int r = sub + 16 * j;
            int row = (int)(block_row + r);
            int s = rs[row];
            int e = s + cnt[row];
            float4 acc = make_float4(0.f, 0.f, 0.f, 0.f);
            for (int i = s; i < e; i++) {
                int2  p = __ldg(&cv[i]);
                float v = __int_as_float(p.y);
                float4 x = X4[(long long)p.x * 16 + g];
                acc.x += v * x.x; acc.y += v * x.y; acc.z += v * x.z; acc.w += v * x.w;
            }
            *(float4*)&hs[r * HS_STRIDE + g * 4] = acc;
        }
    }
    __syncthreads();

    // ---- GEMM phase (identical to proven R2 kernel) ----
    int tx = tid & 15, ty = tid >> 4;
    int o0 = tx * 4;
    float acc[4][4] = {};

    #pragma unroll 4
    for (int k4 = 0; k4 < 32; k4++) {
        float4 wv[4];
        #pragma unroll
        for (int j = 0; j < 4; j++)
            wv[j] = *(const float4*)&ws[(4 * k4 + j) * WS_STRIDE + o0];
        #pragma unroll
        for (int ri = 0; ri < 4; ri++) {
            int r = ty * 4 + ri;
            float4 hv = *(const float4*)&hs[r * HS_STRIDE + k4 * 4];
            acc[ri][0] += hv.x * wv[0].x + hv.y * wv[1].x + hv.z * wv[2].x + hv.w * wv[3].x;
            acc[ri][1] += hv.x * wv[0].y + hv.y * wv[1].y + hv.z * wv[2].y + hv.w * wv[3].y;
            acc[ri][2] += hv.x * wv[0].z + hv.y * wv[1].z + hv.z * wv[2].z + hv.w * wv[3].z;
            acc[ri][3] += hv.x * wv[0].w + hv.y * wv[1].w + hv.z * wv[2].w + hv.w * wv[3].w;
        }
    }

    float b0 = bias[o0 + 0], b1 = bias[o0 + 1], b2 = bias[o0 + 2], b3 = bias[o0 + 3];
    #pragma unroll
    for (int ri = 0; ri < 4; ri++) {
        long long r = block_row + ty * 4 + ri;
        float4 v;
        v.x = fmaxf(acc[ri][0] + b0, 0.f);
        v.y = fmaxf(acc[ri][1] + b1, 0.f);
        v.z = fmaxf(acc[ri][2] + b2, 0.f);
        v.w = fmaxf(acc[ri][3] + b3, 0.f);
        out4[r * 16 + tx] = v;
    }
}

// ---------------------------------------------------------------------------
// Launch (fully serial — overlap experiments regressed; LTS is the shared
// bottleneck, so concurrency only adds interference)
// ---------------------------------------------------------------------------
static void build_csr(const int* rows, const int* cols, const float* vals, int ne,
                      int* cnt, int* rs, int* cur, int* bsum, int2* cv) {
    const int nb_scan = (USER_NUM + 1023) / 1024;          // 196
    const int eb = (ne + 255) / 256;
    zero_int_kernel<<<(USER_NUM + 255) / 256, 256>>>(cnt, USER_NUM);
    hist_kernel<<<eb, 256>>>(rows, cnt, ne);
    block_sum_kernel<<<nb_scan, 256>>>(cnt, bsum, USER_NUM);
    scan_block_kernel<<<nb_scan, 256>>>(cnt, bsum, rs, cur, USER_NUM, nb_scan);
    scatter_kernel<<<eb, 256>>>(rows, cols, vals, cur, cv, ne);
}

extern "C" void kernel_launch(void* const* d_in, const int* in_sizes, int n_in,
                              void* d_out, int out_size) {
    const float* user_emb = (const float*)d_in[0];
    const float* item_emb = (const float*)d_in[1];
    const float* W        = (const float*)d_in[2];
    const float* b        = (const float*)d_in[3];
    const int*   s_rows   = (const int*)  d_in[4];
    const int*   s_cols   = (const int*)  d_in[5];
    const float* s_vals   = (const float*)d_in[6];
    const int*   r_rows   = (const int*)  d_in[7];
    const int*   r_cols   = (const int*)  d_in[8];
    const float* r_vals   = (const float*)d_in[9];
    int ne_s = in_sizes[4];
    int ne_r = in_sizes[7];

    float* out_user = (float*)d_out;
    float* out_item = out_user + (size_t)USER_NUM * EMB;

    float *U1;
    int *cnt, *rs, *cur, *bsum, *cntR, *rsR, *curR, *bsumR;
    int2 *cv, *cvR;
    cudaGetSymbolAddress((void**)&U1,    g_U);
    cudaGetSymbolAddress((void**)&cnt,   g_cnt);
    cudaGetSymbolAddress((void**)&rs,    g_rs);
    cudaGetSymbolAddress((void**)&cur,   g_cur);
    cudaGetSymbolAddress((void**)&bsum,  g_bsum);
    cudaGetSymbolAddress((void**)&cv,    g_cv);
    cudaGetSymbolAddress((void**)&cntR,  g_cntR);
    cudaGetSymbolAddress((void**)&rsR,   g_rsR);
    cudaGetSymbolAddress((void**)&curR,  g_curR);
    cudaGetSymbolAddress((void**)&bsumR, g_bsumR);
    cudaGetSymbolAddress((void**)&cvR,   g_cvR);

    cudaFuncSetAttribute(fused_layer_kernel,
                         cudaFuncAttributeMaxDynamicSharedMemorySize, GEMM_SMEM);

    const int spmm_gb = (USER_NUM * 16 + 255) / 256;   // 12500
    const int gemm_gb = USER_NUM / 64;                 // 3125

    // CSR(S)
    build_csr(s_rows, s_cols, s_vals, ne_s, cnt, rs, cur, bsum, cv);

    // Layer 0 (fused spmm+gemm): U1 = relu([S@U0, U0] W0^T + b0)
    fused_layer_kernel<<<gemm_gb, 256, GEMM_SMEM>>>(rs, cnt, cv, (const float4*)user_emb,
                                                    (const float4*)W, b, (float4*)U1);
    // Layer 1: out_user = relu([S@U1, U1] W1^T + b1)
    fused_layer_kernel<<<gemm_gb, 256, GEMM_SMEM>>>(rs, cnt, cv, (const float4*)U1,
                                                    (const float4*)(W + 64 * 128), b + 64,
                                                    (float4*)out_user);

    // CSR(R) + final accumulate: out_user += R @ V
    build_csr(r_rows, r_cols, r_vals, ne_r, cntR, rsR, curR, bsumR, cvR);
    spmm_csr_kernel<<<spmm_gb, 256>>>(rsR, cntR, cvR, (const float4*)item_emb,
                                      (float4*)out_user);

    // item_all = V
    cudaMemcpyAsync(out_item, item_emb, (size_t)ITEM_NUM * EMB * sizeof(float),
                    cudaMemcpyDeviceToDevice, 0);
}